// round 5
// baseline (speedup 1.0000x reference)
#include <cuda_runtime.h>
#include <cuda_fp16.h>
#include <cstdint>

// Problem dims (fixed)
#define N_TOK   8192
#define D_IN    2048
#define D_OUT   8192

// Tiling
#define BM      128
#define BN      128
#define BK      32
#define NITER   (D_IN / BK)          // 64
#define STAGES  4
#define THREADS 512

#define A_BYTES 8192                 // 128 rows * 32 halves * 2B
#define B_BYTES 8192
#define STG_B   (A_BYTES + 2 * B_BYTES)    // 24576
#define SMEM_BYTES (STAGES * STG_B)        // 98304
#define ELD     132                  // epilogue float stride

// fp16 scratch (device globals; no allocations)
__device__ __align__(1024) __half g_xh [(size_t)N_TOK * D_IN];
__device__ __align__(1024) __half g_kh [(size_t)D_OUT * D_IN];
__device__ __align__(1024) __half g_mh [(size_t)D_OUT * D_IN];

__device__ __forceinline__ uint32_t smem_u32(const void* p) {
    uint32_t a;
    asm("{ .reg .u64 t; cvta.to.shared.u64 t, %1; cvt.u32.u64 %0, t; }" : "=r"(a) : "l"(p));
    return a;
}
__device__ __forceinline__ uint32_t swz(uint32_t off) {   // 128B XOR swizzle
    return off ^ ((off >> 3) & 0x70);
}
__device__ __forceinline__ void cp16(uint32_t sdst, const void* gsrc) {
    asm volatile("cp.async.cg.shared.global [%0], [%1], 16;" :: "r"(sdst), "l"(gsrc));
}
__device__ __forceinline__ void cp_commit() { asm volatile("cp.async.commit_group;"); }

__device__ __forceinline__ void ldsm4(uint32_t* r, uint32_t addr) {
    asm volatile("ldmatrix.sync.aligned.m8n8.x4.shared.b16 {%0,%1,%2,%3}, [%4];"
                 : "=r"(r[0]), "=r"(r[1]), "=r"(r[2]), "=r"(r[3]) : "r"(addr));
}
__device__ __forceinline__ void mma16816(float* c, const uint32_t* a,
                                         uint32_t b0, uint32_t b1) {
    asm volatile(
        "mma.sync.aligned.m16n8k16.row.col.f32.f16.f16.f32 "
        "{%0,%1,%2,%3}, {%4,%5,%6,%7}, {%8,%9}, {%0,%1,%2,%3};"
        : "+f"(c[0]), "+f"(c[1]), "+f"(c[2]), "+f"(c[3])
        : "r"(a[0]), "r"(a[1]), "r"(a[2]), "r"(a[3]), "r"(b0), "r"(b1));
}

// ---------------------------------------------------------------------------
// prep kernels: fp32 -> fp16 (keys = mu * softplus(sigma))
// ---------------------------------------------------------------------------
__global__ void prep_keys_h(const float* __restrict__ mu,
                            const float* __restrict__ sigma,
                            __half* __restrict__ keys, int n4) {
    int i = blockIdx.x * blockDim.x + threadIdx.x;
    int stride = gridDim.x * blockDim.x;
    const float4* m4 = (const float4*)mu;
    const float4* s4 = (const float4*)sigma;
    for (; i < n4; i += stride) {
        float4 m = m4[i], s = s4[i];
        float sp;
        __half o[4];
        sp = (s.x > 20.f) ? s.x : log1pf(expf(s.x)); o[0] = __float2half_rn(m.x * sp);
        sp = (s.y > 20.f) ? s.y : log1pf(expf(s.y)); o[1] = __float2half_rn(m.y * sp);
        sp = (s.z > 20.f) ? s.z : log1pf(expf(s.z)); o[2] = __float2half_rn(m.z * sp);
        sp = (s.w > 20.f) ? s.w : log1pf(expf(s.w)); o[3] = __float2half_rn(m.w * sp);
        *reinterpret_cast<uint2*>(keys + 4 * (size_t)i) = *reinterpret_cast<uint2*>(o);
    }
}
__global__ void f2h_kernel(const float* __restrict__ src,
                           __half* __restrict__ dst, int n4) {
    int i = blockIdx.x * blockDim.x + threadIdx.x;
    int stride = gridDim.x * blockDim.x;
    const float4* s4 = (const float4*)src;
    for (; i < n4; i += stride) {
        float4 v = s4[i];
        __half o[4] = { __float2half_rn(v.x), __float2half_rn(v.y),
                        __float2half_rn(v.z), __float2half_rn(v.w) };
        *reinterpret_cast<uint2*>(dst + 4 * (size_t)i) = *reinterpret_cast<uint2*>(o);
    }
}

// ---------------------------------------------------------------------------
// Fused dual GEMM, GEMM-per-warpgroup split:
//   warps 0-7  : scores = x . keys^T   (acc 64 regs)
//   warps 8-15 : lin    = x . mu^T     (acc 64 regs)
// Epilogue: scores warps publish s via smem; lin warps fuse + store.
// ---------------------------------------------------------------------------
__global__ void __launch_bounds__(THREADS, 1)
sbl_gemm_split(const __half* __restrict__ gx,
               const __half* __restrict__ gk,
               const __half* __restrict__ gm,
               const float* __restrict__ gate,
               const float* __restrict__ bias,
               float* __restrict__ o_final,
               float* __restrict__ o_scores,
               float* __restrict__ o_output) {
    extern __shared__ char smem[];
    const uint32_t sb = smem_u32(smem);
    const int tid = threadIdx.x;
    const int warp = tid >> 5;
    const int lane = tid & 31;
    const int grp = warp >> 3;       // 0 = scores(keys), 1 = lin(mu)
    const int wi = warp & 7;
    const int wm = wi >> 2;          // 0..1  (64-row half)
    const int wn = wi & 3;           // 0..3  (32-col quarter)

    // grid rasterization: GM m-tiles grouped per n sweep (L2 reuse)
    const int num_n = D_OUT / BN;    // 64
    const int GM = 8;
    int pid = blockIdx.x;
    int group = pid / (GM * num_n);
    int within = pid % (GM * num_n);
    const int m_base = (group * GM + (within % GM)) * BM;
    const int n_base = (within / GM) * BN;

    float acc[4][4][4];
    #pragma unroll
    for (int a = 0; a < 4; a++)
        #pragma unroll
        for (int b = 0; b < 4; b++)
            #pragma unroll
            for (int c = 0; c < 4; c++) acc[a][b][c] = 0.f;

    // stage fill: every thread does 3 cp16 (A, Bk, Bm share r,c)
    auto fill = [&](int stage, int k0) {
        uint32_t st = sb + stage * STG_B;
        int r = tid >> 2, c = tid & 3;
        uint32_t so = swz(r * 64 + c * 16);
        cp16(st + so, gx + (size_t)(m_base + r) * D_IN + k0 + c * 8);
        size_t gi = (size_t)(n_base + r) * D_IN + k0 + c * 8;
        cp16(st + A_BYTES + so, gk + gi);
        cp16(st + A_BYTES + B_BYTES + so, gm + gi);
        cp_commit();
    };

    #pragma unroll
    for (int s = 0; s < STAGES - 1; s++) fill(s, s * BK);

    // hoisted ldsm base offsets (kk=0 chunk = lc); per-kk address = base ^ 32
    const int lr = lane & 15;
    const int lc = lane >> 4;
    uint32_t abase[4], bbase[2];
    #pragma unroll
    for (int mf = 0; mf < 4; mf++)
        abase[mf] = swz((wm * 64 + mf * 16 + lr) * 64 + lc * 16);
    const uint32_t bsel = A_BYTES + grp * B_BYTES;
    #pragma unroll
    for (int g = 0; g < 2; g++)
        bbase[g] = bsel + swz((wn * 32 + g * 16 + lr) * 64 + lc * 16);

    for (int ks = 0; ks < NITER; ks++) {
        asm volatile("cp.async.wait_group 2;" ::: "memory");
        __syncthreads();
        if (ks + STAGES - 1 < NITER) fill((ks + STAGES - 1) & 3, (ks + STAGES - 1) * BK);
        else cp_commit();

        const uint32_t st = sb + (ks & 3) * STG_B;

        #pragma unroll
        for (int kk = 0; kk < 2; kk++) {
            const uint32_t kx = kk << 5;
            uint32_t afr[4][4];
            #pragma unroll
            for (int mf = 0; mf < 4; mf++)
                ldsm4(afr[mf], st + (abase[mf] ^ kx));
            uint32_t bf[2][4];
            #pragma unroll
            for (int g = 0; g < 2; g++)
                ldsm4(bf[g], st + (bbase[g] ^ kx));
            #pragma unroll
            for (int mf = 0; mf < 4; mf++)
                #pragma unroll
                for (int nf = 0; nf < 4; nf++)
                    mma16816(acc[mf][nf], afr[mf], bf[nf >> 1][nf & 1], bf[nf >> 1][(nf & 1) + 2]);
        }
    }

    // ---- epilogue: one-way s exchange (scores -> lin warps) ----
    const float scale = 0.022097086912079608f;   // 1/sqrt(2048)
    float* sx = (float*)smem;                    // [128][ELD], 67.6 KB (disjoint from stage 3)
    const int r0base = wm * 64 + (lane >> 2);
    const int cbase  = wn * 32 + (lane & 3) * 2;

    if (grp == 0) {
        #pragma unroll
        for (int mf = 0; mf < 4; mf++) {
            const int r0 = r0base + mf * 16;
            #pragma unroll
            for (int nf = 0; nf < 4; nf++) {
                const int c = cbase + nf * 8;
                *reinterpret_cast<float2*>(sx + r0 * ELD + c) =
                    make_float2(acc[mf][nf][0] * scale, acc[mf][nf][1] * scale);
                *reinterpret_cast<float2*>(sx + (r0 + 8) * ELD + c) =
                    make_float2(acc[mf][nf][2] * scale, acc[mf][nf][3] * scale);
            }
        }
    }
    __syncthreads();

    if (grp == 0) {
        if (o_scores) {
            #pragma unroll
            for (int mf = 0; mf < 4; mf++) {
                const int r0 = m_base + r0base + mf * 16;
                #pragma unroll
                for (int nf = 0; nf < 4; nf++) {
                    const int c = n_base + cbase + nf * 8;
                    *reinterpret_cast<float2*>(o_scores + (size_t)r0 * D_OUT + c) =
                        make_float2(acc[mf][nf][0] * scale, acc[mf][nf][1] * scale);
                    *reinterpret_cast<float2*>(o_scores + (size_t)(r0 + 8) * D_OUT + c) =
                        make_float2(acc[mf][nf][2] * scale, acc[mf][nf][3] * scale);
                }
            }
        }
    } else {
        #pragma unroll
        for (int mf = 0; mf < 4; mf++) {
            const int r0 = r0base + mf * 16;
            #pragma unroll
            for (int nf = 0; nf < 4; nf++) {
                const int c = cbase + nf * 8;
                const float2 s01 = *reinterpret_cast<const float2*>(sx + r0 * ELD + c);
                const float2 s23 = *reinterpret_cast<const float2*>(sx + (r0 + 8) * ELD + c);
                const float2 gt = __ldg(reinterpret_cast<const float2*>(gate + n_base + c));
                const float2 bs = __ldg(reinterpret_cast<const float2*>(bias + n_base + c));
                float v0 = fmaf(fmaxf(s01.x - gt.x, 0.f), acc[mf][nf][0], bs.x);
                float v1 = fmaf(fmaxf(s01.y - gt.y, 0.f), acc[mf][nf][1], bs.y);
                float v2 = fmaf(fmaxf(s23.x - gt.x, 0.f), acc[mf][nf][2], bs.x);
                float v3 = fmaf(fmaxf(s23.y - gt.y, 0.f), acc[mf][nf][3], bs.y);
                size_t o0 = (size_t)(m_base + r0) * D_OUT + n_base + c;
                size_t o1 = (size_t)(m_base + r0 + 8) * D_OUT + n_base + c;
                *reinterpret_cast<float2*>(o_final + o0) = make_float2(v0, v1);
                *reinterpret_cast<float2*>(o_final + o1) = make_float2(v2, v3);
                if (o_output) {
                    *reinterpret_cast<float2*>(o_output + o0) = make_float2(v0, v1);
                    *reinterpret_cast<float2*>(o_output + o1) = make_float2(v2, v3);
                }
            }
        }
    }
}

// ---------------------------------------------------------------------------
extern "C" void kernel_launch(void* const* d_in, const int* in_sizes, int n_in,
                              void* d_out, int out_size) {
    const float* x     = (const float*)d_in[0];
    const float* mu    = (const float*)d_in[1];
    const float* sigma = (const float*)d_in[2];
    const float* gate  = (const float*)d_in[3];
    const float* bias  = (const float*)d_in[4];

    __half *xh, *kh, *mh;
    cudaGetSymbolAddress((void**)&xh, g_xh);
    cudaGetSymbolAddress((void**)&kh, g_kh);
    cudaGetSymbolAddress((void**)&mh, g_mh);

    const size_t n = (size_t)N_TOK * D_OUT;
    float* out = (float*)d_out;
    float* o_final  = out;
    float* o_scores = nullptr;
    float* o_output = nullptr;
    if ((size_t)out_size >= 3 * n)      { o_scores = out + n; o_output = out + 2 * n; }
    else if ((size_t)out_size >= 2 * n) { o_scores = out + n; }

    f2h_kernel<<<2048, 256>>>(x, xh, (N_TOK * D_IN) / 4);
    f2h_kernel<<<2048, 256>>>(mu, mh, (D_OUT * D_IN) / 4);
    prep_keys_h<<<2048, 256>>>(mu, sigma, kh, (D_OUT * D_IN) / 4);

    cudaFuncSetAttribute(sbl_gemm_split,
                         cudaFuncAttributeMaxDynamicSharedMemorySize, SMEM_BYTES);
    dim3 grid((N_TOK / BM) * (D_OUT / BN));   // 4096 CTAs
    sbl_gemm_split<<<grid, THREADS, SMEM_BYTES>>>(xh, kh, mh, gate, bias,
                                                  o_final, o_scores, o_output);
}

// round 6
// speedup vs baseline: 1.1345x; 1.1345x over previous
#include <cuda_runtime.h>
#include <cuda_fp16.h>
#include <cstdint>

// Problem dims (fixed)
#define N_TOK   8192
#define D_IN    2048
#define D_OUT   8192

// Tiling
#define BM      128
#define BN      128
#define BK      32
#define NITER   (D_IN / BK)          // 64
#define STAGES  4
#define THREADS 256

#define A_TILE_B  8192               // 128 x 32 halves
#define W_TILE_B  16384              // keys tile + mu tile
#define STG_B     (A_TILE_B + W_TILE_B)      // 24576
#define SMEM_DATA (STAGES * STG_B)           // 98304
#define SMEM_BYTES (1024 + SMEM_DATA)        // 99328

#define NUM_MT  (N_TOK / BM)         // 64
#define NUM_NT  (D_OUT / BN)         // 64
#define NUM_KT  (D_IN / BK)          // 64

// Pre-swizzled, tile-contiguous fp16 scratch (device globals; no allocations)
// g_xh: [mt][kt][8KB]   g_wh: [nt][kt][ keys 8KB | mu 8KB ]
__device__ __align__(1024) char g_xh[(size_t)NUM_MT * NUM_KT * A_TILE_B];
__device__ __align__(1024) char g_wh[(size_t)NUM_NT * NUM_KT * W_TILE_B];

__device__ __forceinline__ uint32_t smem_u32(const void* p) {
    uint32_t a;
    asm("{ .reg .u64 t; cvta.to.shared.u64 t, %1; cvt.u32.u64 %0, t; }" : "=r"(a) : "l"(p));
    return a;
}
__device__ __forceinline__ uint32_t swz(uint32_t off) {   // 128B XOR swizzle (involution)
    return off ^ ((off >> 3) & 0x70);
}
__device__ __forceinline__ void ldsm4(uint32_t* r, uint32_t addr) {
    asm volatile("ldmatrix.sync.aligned.m8n8.x4.shared.b16 {%0,%1,%2,%3}, [%4];"
                 : "=r"(r[0]), "=r"(r[1]), "=r"(r[2]), "=r"(r[3]) : "r"(addr));
}
__device__ __forceinline__ void mma16816(float* c, const uint32_t* a,
                                         uint32_t b0, uint32_t b1) {
    asm volatile(
        "mma.sync.aligned.m16n8k16.row.col.f32.f16.f16.f32 "
        "{%0,%1,%2,%3}, {%4,%5,%6,%7}, {%8,%9}, {%0,%1,%2,%3};"
        : "+f"(c[0]), "+f"(c[1]), "+f"(c[2]), "+f"(c[3])
        : "r"(a[0]), "r"(a[1]), "r"(a[2]), "r"(a[3]), "r"(b0), "r"(b1));
}
__device__ __forceinline__ void mbar_init(uint32_t a, uint32_t cnt) {
    asm volatile("mbarrier.init.shared.b64 [%0], %1;" :: "r"(a), "r"(cnt) : "memory");
}
__device__ __forceinline__ void mbar_arrive(uint32_t a) {
    asm volatile("mbarrier.arrive.shared.b64 _, [%0];" :: "r"(a) : "memory");
}
__device__ __forceinline__ void mbar_expect_tx(uint32_t a, uint32_t bytes) {
    asm volatile("mbarrier.arrive.expect_tx.shared.b64 _, [%0], %1;"
                 :: "r"(a), "r"(bytes) : "memory");
}
__device__ __forceinline__ void mbar_wait(uint32_t a, uint32_t parity) {
    asm volatile(
        "{\n\t.reg .pred P;\n\t"
        "WL_%=:\n\t"
        "mbarrier.try_wait.parity.acquire.cta.shared::cta.b64 P, [%0], %1, 0x989680;\n\t"
        "@P bra.uni WD_%=;\n\t"
        "bra.uni WL_%=;\n\t"
        "WD_%=:\n\t}"
        :: "r"(a), "r"(parity) : "memory");
}
__device__ __forceinline__ void bulk_ld(uint32_t sdst, const void* gsrc,
                                        uint32_t bytes, uint32_t mbar) {
    asm volatile(
        "cp.async.bulk.shared::cluster.global.mbarrier::complete_tx::bytes "
        "[%0], [%1], %2, [%3];"
        :: "r"(sdst), "l"(gsrc), "r"(bytes), "r"(mbar) : "memory");
}

// ---------------------------------------------------------------------------
// prep: write tile-contiguous, pre-swizzled fp16 tiles (dst-coalesced)
// ---------------------------------------------------------------------------
__global__ void prep_x_tiled(const float* __restrict__ x, char* __restrict__ dst) {
    const int total = NUM_MT * NUM_KT * (A_TILE_B / 16);   // 16B chunks
    int id = blockIdx.x * blockDim.x + threadIdx.x;
    int stride = gridDim.x * blockDim.x;
    for (; id < total; id += stride) {
        int t = id >> 9;                 // tile index (512 chunks / 8KB tile)
        uint32_t w = (id & 511) * 16;    // dst byte within tile
        uint32_t u = swz(w);             // logical offset (involution)
        int r = u >> 6, c = (u >> 4) & 3;
        int mt = t >> 6, kt = t & 63;
        const float* src = x + (size_t)(mt * 128 + r) * D_IN + kt * 32 + c * 8;
        float4 a = *reinterpret_cast<const float4*>(src);
        float4 b = *reinterpret_cast<const float4*>(src + 4);
        __half o[8] = { __float2half_rn(a.x), __float2half_rn(a.y),
                        __float2half_rn(a.z), __float2half_rn(a.w),
                        __float2half_rn(b.x), __float2half_rn(b.y),
                        __float2half_rn(b.z), __float2half_rn(b.w) };
        *reinterpret_cast<uint4*>(dst + (size_t)id * 16) = *reinterpret_cast<uint4*>(o);
    }
}
__global__ void prep_w_tiled(const float* __restrict__ mu,
                             const float* __restrict__ sigma,
                             char* __restrict__ dst) {
    const int total = NUM_NT * NUM_KT * (W_TILE_B / 16);
    int id = blockIdx.x * blockDim.x + threadIdx.x;
    int stride = gridDim.x * blockDim.x;
    for (; id < total; id += stride) {
        int t = id >> 10;                    // tile (1024 chunks / 16KB)
        int within = id & 1023;
        int half = within >> 9;              // 0 = keys, 1 = mu
        uint32_t w = (within & 511) * 16;
        uint32_t u = swz(w);
        int r = u >> 6, c = (u >> 4) & 3;
        int nt = t >> 6, kt = t & 63;
        const size_t so = (size_t)(nt * 128 + r) * D_IN + kt * 32 + c * 8;
        float4 a = *reinterpret_cast<const float4*>(mu + so);
        float4 b = *reinterpret_cast<const float4*>(mu + so + 4);
        float v[8] = { a.x, a.y, a.z, a.w, b.x, b.y, b.z, b.w };
        if (half == 0) {
            float4 sa = *reinterpret_cast<const float4*>(sigma + so);
            float4 sb = *reinterpret_cast<const float4*>(sigma + so + 4);
            float sg[8] = { sa.x, sa.y, sa.z, sa.w, sb.x, sb.y, sb.z, sb.w };
            #pragma unroll
            for (int q = 0; q < 8; q++) {
                float sp = (sg[q] > 20.f) ? sg[q] : log1pf(expf(sg[q]));
                v[q] *= sp;
            }
        }
        __half o[8];
        #pragma unroll
        for (int q = 0; q < 8; q++) o[q] = __float2half_rn(v[q]);
        *reinterpret_cast<uint4*>(dst + (size_t)id * 16) = *reinterpret_cast<uint4*>(o);
    }
}

// ---------------------------------------------------------------------------
// Fused dual GEMM: bulk-copy producer (mbarrier ring) + mma.m16n8k16 consumer.
// 8 warps: wm = warp>>2 (M 64-half), wn = warp&3 (N 32-quarter); dual acc.
// ---------------------------------------------------------------------------
__global__ void __launch_bounds__(THREADS, 1)
sbl_gemm_bulk(const char* __restrict__ gA,
              const char* __restrict__ gW,
              const float* __restrict__ gate,
              const float* __restrict__ bias,
              float* __restrict__ o_final,
              float* __restrict__ o_scores,
              float* __restrict__ o_output) {
    extern __shared__ char smem[];
    const uint32_t sb = smem_u32(smem);
    const int tid = threadIdx.x;
    const int warp = tid >> 5;
    const int lane = tid & 31;
    const int wm = warp >> 2;
    const int wn = warp & 3;

    // raster: GM m-tiles per n sweep (L2 reuse of W panels)
    const int GM = 8;
    int pid = blockIdx.x;
    int group = pid / (GM * NUM_NT);
    int within = pid % (GM * NUM_NT);
    const int m_idx = group * GM + (within % GM);
    const int n_idx = within / GM;
    const int m_base = m_idx * BM;
    const int n_base = n_idx * BN;

    const char* Abase = gA + (size_t)m_idx * NUM_KT * A_TILE_B;
    const char* Wbase = gW + (size_t)n_idx * NUM_KT * W_TILE_B;

    // barriers: full[s] = sb + s*16, empty[s] = sb + s*16 + 8
    if (tid == 0) {
        #pragma unroll
        for (int s = 0; s < STAGES; s++) {
            mbar_init(sb + s * 16, 1);       // full: expect_tx arrive
            mbar_init(sb + s * 16 + 8, 8);   // empty: 8 warp arrivals
        }
    }
    __syncthreads();

    float acc_s[4][4][4], acc_l[4][4][4];
    #pragma unroll
    for (int a = 0; a < 4; a++)
        #pragma unroll
        for (int b = 0; b < 4; b++)
            #pragma unroll
            for (int c = 0; c < 4; c++) { acc_s[a][b][c] = 0.f; acc_l[a][b][c] = 0.f; }

    auto fill = [&](int kt) {
        const int s = kt & 3;
        mbar_wait(sb + s * 16 + 8, ((kt >> 2) & 1) ^ 1);   // empty, producer parity
        const uint32_t full = sb + s * 16;
        mbar_expect_tx(full, STG_B);
        const uint32_t st = sb + 1024 + s * STG_B;
        bulk_ld(st, Abase + (size_t)kt * A_TILE_B, A_TILE_B, full);
        bulk_ld(st + A_TILE_B, Wbase + (size_t)kt * W_TILE_B, W_TILE_B, full);
    };

    if (tid == 0) { fill(0); fill(1); fill(2); }

    // hoisted ldsm base offsets; per-kk address = base ^ 32
    const int lr = lane & 15;
    const int lc = lane >> 4;
    uint32_t abase[4], bkb[2], bmb[2];
    #pragma unroll
    for (int mf = 0; mf < 4; mf++)
        abase[mf] = swz((wm * 64 + mf * 16 + lr) * 64 + lc * 16);
    #pragma unroll
    for (int g = 0; g < 2; g++) {
        uint32_t o = swz((wn * 32 + g * 16 + lr) * 64 + lc * 16);
        bkb[g] = A_TILE_B + o;
        bmb[g] = A_TILE_B + 8192 + o;
    }

    for (int ks = 0; ks < NITER; ks++) {
        const int cur = ks & 3;
        if (tid == 0 && ks + 3 < NITER) fill(ks + 3);
        mbar_wait(sb + cur * 16, (ks >> 2) & 1);           // full, consumer parity
        const uint32_t st = sb + 1024 + cur * STG_B;

        #pragma unroll
        for (int kk = 0; kk < 2; kk++) {
            const uint32_t kx = kk << 5;
            uint32_t afr[4][4];
            #pragma unroll
            for (int mf = 0; mf < 4; mf++)
                ldsm4(afr[mf], st + (abase[mf] ^ kx));
            uint32_t bkf[2][4], bmf[2][4];
            #pragma unroll
            for (int g = 0; g < 2; g++) {
                ldsm4(bkf[g], st + (bkb[g] ^ kx));
                ldsm4(bmf[g], st + (bmb[g] ^ kx));
            }
            #pragma unroll
            for (int mf = 0; mf < 4; mf++)
                #pragma unroll
                for (int nf = 0; nf < 4; nf++) {
                    const int g = nf >> 1, sel = nf & 1;
                    mma16816(acc_s[mf][nf], afr[mf], bkf[g][sel], bkf[g][sel + 2]);
                    mma16816(acc_l[mf][nf], afr[mf], bmf[g][sel], bmf[g][sel + 2]);
                }
        }
        if (lane == 0) mbar_arrive(sb + cur * 16 + 8);     // empty arrive (per warp)
    }

    // ---- register epilogue ----
    const float scale = 0.022097086912079608f;   // 1/sqrt(2048)
    const int r0base = m_base + wm * 64 + (lane >> 2);
    const int cbase  = n_base + wn * 32 + (lane & 3) * 2;

    #pragma unroll
    for (int mf = 0; mf < 4; mf++) {
        const int r0 = r0base + mf * 16;
        #pragma unroll
        for (int nf = 0; nf < 4; nf++) {
            const int c = cbase + nf * 8;
            const float2 gt = __ldg(reinterpret_cast<const float2*>(gate + c));
            const float2 bs = __ldg(reinterpret_cast<const float2*>(bias + c));
            float s0 = acc_s[mf][nf][0] * scale;
            float s1 = acc_s[mf][nf][1] * scale;
            float s2 = acc_s[mf][nf][2] * scale;
            float s3 = acc_s[mf][nf][3] * scale;
            float v0 = fmaf(fmaxf(s0 - gt.x, 0.f), acc_l[mf][nf][0], bs.x);
            float v1 = fmaf(fmaxf(s1 - gt.y, 0.f), acc_l[mf][nf][1], bs.y);
            float v2 = fmaf(fmaxf(s2 - gt.x, 0.f), acc_l[mf][nf][2], bs.x);
            float v3 = fmaf(fmaxf(s3 - gt.y, 0.f), acc_l[mf][nf][3], bs.y);
            size_t o0 = (size_t)r0 * D_OUT + c;
            size_t o1 = (size_t)(r0 + 8) * D_OUT + c;
            *reinterpret_cast<float2*>(o_final + o0) = make_float2(v0, v1);
            *reinterpret_cast<float2*>(o_final + o1) = make_float2(v2, v3);
            if (o_scores) {
                *reinterpret_cast<float2*>(o_scores + o0) = make_float2(s0, s1);
                *reinterpret_cast<float2*>(o_scores + o1) = make_float2(s2, s3);
            }
            if (o_output) {
                *reinterpret_cast<float2*>(o_output + o0) = make_float2(v0, v1);
                *reinterpret_cast<float2*>(o_output + o1) = make_float2(v2, v3);
            }
        }
    }
}

// ---------------------------------------------------------------------------
extern "C" void kernel_launch(void* const* d_in, const int* in_sizes, int n_in,
                              void* d_out, int out_size) {
    const float* x     = (const float*)d_in[0];
    const float* mu    = (const float*)d_in[1];
    const float* sigma = (const float*)d_in[2];
    const float* gate  = (const float*)d_in[3];
    const float* bias  = (const float*)d_in[4];

    char *gA, *gW;
    cudaGetSymbolAddress((void**)&gA, g_xh);
    cudaGetSymbolAddress((void**)&gW, g_wh);

    const size_t n = (size_t)N_TOK * D_OUT;
    float* out = (float*)d_out;
    float* o_final  = out;
    float* o_scores = nullptr;
    float* o_output = nullptr;
    if ((size_t)out_size >= 3 * n)      { o_scores = out + n; o_output = out + 2 * n; }
    else if ((size_t)out_size >= 2 * n) { o_scores = out + n; }

    prep_x_tiled<<<4096, 256>>>(x, gA);
    prep_w_tiled<<<8192, 256>>>(mu, sigma, gW);

    cudaFuncSetAttribute(sbl_gemm_bulk,
                         cudaFuncAttributeMaxDynamicSharedMemorySize, SMEM_BYTES);
    dim3 grid(NUM_MT * NUM_NT);   // 4096 CTAs
    sbl_gemm_bulk<<<grid, THREADS, SMEM_BYTES>>>(gA, gW, gate, bias,
                                                 o_final, o_scores, o_output);
}

// round 7
// speedup vs baseline: 1.2362x; 1.0896x over previous
#include <cuda_runtime.h>
#include <cuda_fp16.h>
#include <cstdint>

// Problem dims (fixed)
#define N_TOK   8192
#define D_IN    2048
#define D_OUT   8192

// Tiling
#define BM      128
#define BN      128
#define BK      64
#define NITER   (D_IN / BK)          // 32
#define STAGES  4
#define THREADS 256

#define A_TILE_B  16384              // 128 rows x 128B (64 halves)
#define W_TILE_B  32768              // keys 16KB + mu 16KB
#define STG_B     (A_TILE_B + W_TILE_B)      // 49152
#define SMEM_BYTES (1024 + STAGES * STG_B)   // 197632

#define NUM_MT  (N_TOK / BM)         // 64
#define NUM_NT  (D_OUT / BN)         // 64
#define NUM_KT  (D_IN / BK)          // 32

// Pre-swizzled, tile-contiguous fp16 scratch (device globals; no allocations)
// g_xh: [mt][kt][16KB]   g_wh: [nt][kt][ keys 16KB | mu 16KB ]
__device__ __align__(1024) char g_xh[(size_t)NUM_MT * NUM_KT * A_TILE_B];
__device__ __align__(1024) char g_wh[(size_t)NUM_NT * NUM_KT * W_TILE_B];

__device__ __forceinline__ uint32_t smem_u32(const void* p) {
    uint32_t a;
    asm("{ .reg .u64 t; cvta.to.shared.u64 t, %1; cvt.u32.u64 %0, t; }" : "=r"(a) : "l"(p));
    return a;
}
__device__ __forceinline__ uint32_t swz(uint32_t off) {   // SW128 XOR swizzle (involution)
    return off ^ ((off >> 3) & 0x70);
}
__device__ __forceinline__ void ldsm4(uint32_t* r, uint32_t addr) {
    asm volatile("ldmatrix.sync.aligned.m8n8.x4.shared.b16 {%0,%1,%2,%3}, [%4];"
                 : "=r"(r[0]), "=r"(r[1]), "=r"(r[2]), "=r"(r[3]) : "r"(addr));
}
__device__ __forceinline__ void mma16816(float* c, const uint32_t* a,
                                         uint32_t b0, uint32_t b1) {
    asm volatile(
        "mma.sync.aligned.m16n8k16.row.col.f32.f16.f16.f32 "
        "{%0,%1,%2,%3}, {%4,%5,%6,%7}, {%8,%9}, {%0,%1,%2,%3};"
        : "+f"(c[0]), "+f"(c[1]), "+f"(c[2]), "+f"(c[3])
        : "r"(a[0]), "r"(a[1]), "r"(a[2]), "r"(a[3]), "r"(b0), "r"(b1));
}
__device__ __forceinline__ void mbar_init(uint32_t a, uint32_t cnt) {
    asm volatile("mbarrier.init.shared.b64 [%0], %1;" :: "r"(a), "r"(cnt) : "memory");
}
__device__ __forceinline__ void mbar_arrive(uint32_t a) {
    asm volatile("mbarrier.arrive.shared.b64 _, [%0];" :: "r"(a) : "memory");
}
__device__ __forceinline__ void mbar_expect_tx(uint32_t a, uint32_t bytes) {
    asm volatile("mbarrier.arrive.expect_tx.shared.b64 _, [%0], %1;"
                 :: "r"(a), "r"(bytes) : "memory");
}
__device__ __forceinline__ void mbar_wait(uint32_t a, uint32_t parity) {
    asm volatile(
        "{\n\t.reg .pred P;\n\t"
        "WL_%=:\n\t"
        "mbarrier.try_wait.parity.acquire.cta.shared::cta.b64 P, [%0], %1, 0x989680;\n\t"
        "@P bra.uni WD_%=;\n\t"
        "bra.uni WL_%=;\n\t"
        "WD_%=:\n\t}"
        :: "r"(a), "r"(parity) : "memory");
}
__device__ __forceinline__ void bulk_ld(uint32_t sdst, const void* gsrc,
                                        uint32_t bytes, uint32_t mbar) {
    asm volatile(
        "cp.async.bulk.shared::cluster.global.mbarrier::complete_tx::bytes "
        "[%0], [%1], %2, [%3];"
        :: "r"(sdst), "l"(gsrc), "r"(bytes), "r"(mbar) : "memory");
}

// ---------------------------------------------------------------------------
// prep: write tile-contiguous, pre-swizzled fp16 tiles (dst-coalesced)
// tile = 128 rows x 128B (64 halves of K)
// ---------------------------------------------------------------------------
__global__ void prep_x_tiled(const float* __restrict__ x, char* __restrict__ dst) {
    const int total = NUM_MT * NUM_KT * (A_TILE_B / 16);   // 16B chunks
    int id = blockIdx.x * blockDim.x + threadIdx.x;
    int stride = gridDim.x * blockDim.x;
    for (; id < total; id += stride) {
        int t = id >> 10;                 // tile index (1024 chunks / 16KB)
        uint32_t w = (id & 1023) * 16;    // dst byte within tile
        uint32_t u = swz(w);              // logical offset (involution)
        int r = u >> 7, c = (u >> 4) & 7;
        int mt = t >> 5, kt = t & 31;
        const float* src = x + (size_t)(mt * 128 + r) * D_IN + kt * 64 + c * 8;
        float4 a = *reinterpret_cast<const float4*>(src);
        float4 b = *reinterpret_cast<const float4*>(src + 4);
        __half o[8] = { __float2half_rn(a.x), __float2half_rn(a.y),
                        __float2half_rn(a.z), __float2half_rn(a.w),
                        __float2half_rn(b.x), __float2half_rn(b.y),
                        __float2half_rn(b.z), __float2half_rn(b.w) };
        *reinterpret_cast<uint4*>(dst + (size_t)id * 16) = *reinterpret_cast<uint4*>(o);
    }
}
__global__ void prep_w_tiled(const float* __restrict__ mu,
                             const float* __restrict__ sigma,
                             char* __restrict__ dst) {
    const int total = NUM_NT * NUM_KT * (W_TILE_B / 16);
    int id = blockIdx.x * blockDim.x + threadIdx.x;
    int stride = gridDim.x * blockDim.x;
    for (; id < total; id += stride) {
        int t = id >> 11;                    // tile (2048 chunks / 32KB)
        int within = id & 2047;
        int half = within >> 10;             // 0 = keys, 1 = mu
        uint32_t w = (within & 1023) * 16;
        uint32_t u = swz(w);
        int r = u >> 7, c = (u >> 4) & 7;
        int nt = t >> 5, kt = t & 31;
        const size_t so = (size_t)(nt * 128 + r) * D_IN + kt * 64 + c * 8;
        float4 a = *reinterpret_cast<const float4*>(mu + so);
        float4 b = *reinterpret_cast<const float4*>(mu + so + 4);
        float v[8] = { a.x, a.y, a.z, a.w, b.x, b.y, b.z, b.w };
        if (half == 0) {
            float4 sa = *reinterpret_cast<const float4*>(sigma + so);
            float4 sb = *reinterpret_cast<const float4*>(sigma + so + 4);
            float sg[8] = { sa.x, sa.y, sa.z, sa.w, sb.x, sb.y, sb.z, sb.w };
            #pragma unroll
            for (int q = 0; q < 8; q++) {
                float sp = (sg[q] > 20.f) ? sg[q] : log1pf(expf(sg[q]));
                v[q] *= sp;
            }
        }
        __half o[8];
        #pragma unroll
        for (int q = 0; q < 8; q++) o[q] = __float2half_rn(v[q]);
        *reinterpret_cast<uint4*>(dst + (size_t)id * 16) = *reinterpret_cast<uint4*>(o);
    }
}

// ---------------------------------------------------------------------------
// Fused dual GEMM: bulk-copy producer + mma.m16n8k16 consumer.
// BK=64, fragment double-buffer hides LDSM latency within a stage.
// 8 warps: wm = warp>>2 (M 64-half), wn = warp&3 (N 32-quarter); dual acc.
// ---------------------------------------------------------------------------
__global__ void __launch_bounds__(THREADS, 1)
sbl_gemm_bulk(const char* __restrict__ gA,
              const char* __restrict__ gW,
              const float* __restrict__ gate,
              const float* __restrict__ bias,
              float* __restrict__ o_final,
              float* __restrict__ o_scores,
              float* __restrict__ o_output) {
    extern __shared__ char smem[];
    const uint32_t sb = smem_u32(smem);
    const int tid = threadIdx.x;
    const int warp = tid >> 5;
    const int lane = tid & 31;
    const int wm = warp >> 2;
    const int wn = warp & 3;

    // raster: GM m-tiles per n sweep (L2 reuse of W panels)
    const int GM = 8;
    int pid = blockIdx.x;
    int group = pid / (GM * NUM_NT);
    int within = pid % (GM * NUM_NT);
    const int m_idx = group * GM + (within % GM);
    const int n_idx = within / GM;
    const int m_base = m_idx * BM;
    const int n_base = n_idx * BN;

    const char* Abase = gA + (size_t)m_idx * NUM_KT * A_TILE_B;
    const char* Wbase = gW + (size_t)n_idx * NUM_KT * W_TILE_B;

    // barriers: full[s] = sb + s*16, empty[s] = sb + s*16 + 8
    if (tid == 0) {
        #pragma unroll
        for (int s = 0; s < STAGES; s++) {
            mbar_init(sb + s * 16, 1);       // full: expect_tx arrive
            mbar_init(sb + s * 16 + 8, 8);   // empty: 8 warp arrivals
        }
    }
    __syncthreads();

    float acc_s[4][4][4], acc_l[4][4][4];
    #pragma unroll
    for (int a = 0; a < 4; a++)
        #pragma unroll
        for (int b = 0; b < 4; b++)
            #pragma unroll
            for (int c = 0; c < 4; c++) { acc_s[a][b][c] = 0.f; acc_l[a][b][c] = 0.f; }

    auto fill = [&](int kt) {
        const int s = kt & 3;
        mbar_wait(sb + s * 16 + 8, ((kt >> 2) & 1) ^ 1);   // empty, producer parity
        const uint32_t full = sb + s * 16;
        mbar_expect_tx(full, STG_B);
        const uint32_t st = sb + 1024 + s * STG_B;
        bulk_ld(st, Abase + (size_t)kt * A_TILE_B, A_TILE_B, full);
        bulk_ld(st + A_TILE_B, Wbase + (size_t)kt * W_TILE_B, W_TILE_B, full);
    };

    if (tid == 0) { fill(0); fill(1); fill(2); }

    // hoisted ldsm base offsets; per-kk address = base ^ (kk<<5) (exact, no carry)
    const int lr = lane & 15;
    const int lc = lane >> 4;
    uint32_t abase[4], bkb[2], bmb[2];
    #pragma unroll
    for (int mf = 0; mf < 4; mf++)
        abase[mf] = swz((wm * 64 + mf * 16 + lr) * 128 + lc * 16);
    #pragma unroll
    for (int g = 0; g < 2; g++) {
        uint32_t o = swz((wn * 32 + g * 16 + lr) * 128 + lc * 16);
        bkb[g] = A_TILE_B + o;
        bmb[g] = A_TILE_B + 16384 + o;
    }

    uint32_t afr[2][4][4], bkf[2][2][4], bmf[2][2][4];

    auto load_frags = [&](int buf, uint32_t st, int kk) {
        const uint32_t kx = (uint32_t)kk << 5;
        #pragma unroll
        for (int mf = 0; mf < 4; mf++)
            ldsm4(afr[buf][mf], st + (abase[mf] ^ kx));
        #pragma unroll
        for (int g = 0; g < 2; g++) {
            ldsm4(bkf[buf][g], st + (bkb[g] ^ kx));
            ldsm4(bmf[buf][g], st + (bmb[g] ^ kx));
        }
    };
    auto do_mma = [&](int buf) {
        #pragma unroll
        for (int mf = 0; mf < 4; mf++)
            #pragma unroll
            for (int nf = 0; nf < 4; nf++) {
                const int g = nf >> 1, sel = nf & 1;
                mma16816(acc_s[mf][nf], afr[buf][mf], bkf[buf][g][sel], bkf[buf][g][sel + 2]);
                mma16816(acc_l[mf][nf], afr[buf][mf], bmf[buf][g][sel], bmf[buf][g][sel + 2]);
            }
    };

    for (int ks = 0; ks < NITER; ks++) {
        const int cur = ks & 3;
        if (tid == 0 && ks + 3 < NITER) fill(ks + 3);
        mbar_wait(sb + cur * 16, (ks >> 2) & 1);           // full, consumer parity
        const uint32_t st = sb + 1024 + cur * STG_B;

        load_frags(0, st, 0);
        #pragma unroll
        for (int kk = 0; kk < 4; kk++) {
            if (kk < 3) load_frags((kk + 1) & 1, st, kk + 1);
            do_mma(kk & 1);
        }
        if (lane == 0) mbar_arrive(sb + cur * 16 + 8);     // empty arrive (per warp)
    }

    // ---- register epilogue ----
    const float scale = 0.022097086912079608f;   // 1/sqrt(2048)
    const int r0base = m_base + wm * 64 + (lane >> 2);
    const int cbase  = n_base + wn * 32 + (lane & 3) * 2;

    #pragma unroll
    for (int mf = 0; mf < 4; mf++) {
        const int r0 = r0base + mf * 16;
        #pragma unroll
        for (int nf = 0; nf < 4; nf++) {
            const int c = cbase + nf * 8;
            const float2 gt = __ldg(reinterpret_cast<const float2*>(gate + c));
            const float2 bs = __ldg(reinterpret_cast<const float2*>(bias + c));
            float s0 = acc_s[mf][nf][0] * scale;
            float s1 = acc_s[mf][nf][1] * scale;
            float s2 = acc_s[mf][nf][2] * scale;
            float s3 = acc_s[mf][nf][3] * scale;
            float v0 = fmaf(fmaxf(s0 - gt.x, 0.f), acc_l[mf][nf][0], bs.x);
            float v1 = fmaf(fmaxf(s1 - gt.y, 0.f), acc_l[mf][nf][1], bs.y);
            float v2 = fmaf(fmaxf(s2 - gt.x, 0.f), acc_l[mf][nf][2], bs.x);
            float v3 = fmaf(fmaxf(s3 - gt.y, 0.f), acc_l[mf][nf][3], bs.y);
            size_t o0 = (size_t)r0 * D_OUT + c;
            size_t o1 = (size_t)(r0 + 8) * D_OUT + c;
            *reinterpret_cast<float2*>(o_final + o0) = make_float2(v0, v1);
            *reinterpret_cast<float2*>(o_final + o1) = make_float2(v2, v3);
            if (o_scores) {
                *reinterpret_cast<float2*>(o_scores + o0) = make_float2(s0, s1);
                *reinterpret_cast<float2*>(o_scores + o1) = make_float2(s2, s3);
            }
            if (o_output) {
                *reinterpret_cast<float2*>(o_output + o0) = make_float2(v0, v1);
                *reinterpret_cast<float2*>(o_output + o1) = make_float2(v2, v3);
            }
        }
    }
}

// ---------------------------------------------------------------------------
extern "C" void kernel_launch(void* const* d_in, const int* in_sizes, int n_in,
                              void* d_out, int out_size) {
    const float* x     = (const float*)d_in[0];
    const float* mu    = (const float*)d_in[1];
    const float* sigma = (const float*)d_in[2];
    const float* gate  = (const float*)d_in[3];
    const float* bias  = (const float*)d_in[4];

    char *gA, *gW;
    cudaGetSymbolAddress((void**)&gA, g_xh);
    cudaGetSymbolAddress((void**)&gW, g_wh);

    const size_t n = (size_t)N_TOK * D_OUT;
    float* out = (float*)d_out;
    float* o_final  = out;
    float* o_scores = nullptr;
    float* o_output = nullptr;
    if ((size_t)out_size >= 3 * n)      { o_scores = out + n; o_output = out + 2 * n; }
    else if ((size_t)out_size >= 2 * n) { o_scores = out + n; }

    prep_x_tiled<<<4096, 256>>>(x, gA);
    prep_w_tiled<<<8192, 256>>>(mu, sigma, gW);

    cudaFuncSetAttribute(sbl_gemm_bulk,
                         cudaFuncAttributeMaxDynamicSharedMemorySize, SMEM_BYTES);
    dim3 grid(NUM_MT * NUM_NT);   // 4096 CTAs
    sbl_gemm_bulk<<<grid, THREADS, SMEM_BYTES>>>(gA, gW, gate, bias,
                                                 o_final, o_scores, o_output);
}